// round 12
// baseline (speedup 1.0000x reference)
#include <cuda_runtime.h>
#include <cuda_fp16.h>

// Trilinear resample, zero boundary.
// inputs:      [B=2, X=144, Y=144, Z=144, C=2] fp32
// deformation: [B, X, Y, Z, 3] fp32 absolute voxel coords
// output:      [B, X, Y, Z, C] fp32
//
// Per-batch table (47.8 MB, L2-resident): T[x][y][z] = 8 fp16 = 2x2 (y,z)
// corner block, 2 ch, zero-padded at y/z upper edges. Sequence per batch:
// expand(b), main(b). evict_last on table, def/out stream. Main: 2 voxels
// per thread with ALL FOUR 16B gathers issued before any consumption.

#define SX 144
#define SY 144
#define SZ 144
#define NC 2
#define NB 2
#define VOL (SX * SY * SZ)

__device__ uint4 g_exp[(size_t)VOL];   // one batch's table

static __device__ __forceinline__ unsigned pack_h2(float a, float b) {
    __half2 h = __floats2half2_rn(a, b);
    return *(unsigned*)&h;
}
static __device__ __forceinline__ float2 unpack_h2(unsigned u) {
    __half2 h = *(__half2*)&u;
    return __half22float2(h);
}

static __device__ __forceinline__ unsigned long long evict_last_policy() {
    unsigned long long pol;
    asm("createpolicy.fractional.L2::evict_last.b64 %0, 1.0;" : "=l"(pol));
    return pol;
}
static __device__ __forceinline__ void st_evict_last(
    uint4* p, uint4 v, unsigned long long pol) {
    asm volatile("st.global.L2::cache_hint.v4.b32 [%0], {%1,%2,%3,%4}, %5;"
                 :: "l"(p), "r"(v.x), "r"(v.y), "r"(v.z), "r"(v.w), "l"(pol)
                 : "memory");
}
static __device__ __forceinline__ uint4 ld_evict_last(
    const uint4* p, unsigned long long pol) {
    uint4 v;
    asm("ld.global.nc.L2::cache_hint.v4.b32 {%0,%1,%2,%3}, [%4], %5;"
        : "=r"(v.x), "=r"(v.y), "=r"(v.z), "=r"(v.w) : "l"(p), "l"(pol));
    return v;
}

// Prep for one batch: entry idx = x*SY*SZ + y*SZ + z (batch-local).
__global__ __launch_bounds__(256) void expand_kernel(
    const float* __restrict__ inpb, int n)   // n = VOL
{
    int idx = blockIdx.x * blockDim.x + threadIdx.x;
    if (idx >= n) return;

    int z = idx % SZ;
    int r = idx / SZ;
    int y = r % SY;

    const float* p00 = inpb + (size_t)idx * NC;  // (y, z)
    bool zv = (z + 1 < SZ);
    bool yv = (y + 1 < SY);

    float2 v00 = *(const float2*)p00;
    float2 v01 = zv ? *(const float2*)(p00 + NC) : make_float2(0.f, 0.f);
    float2 v10 = yv ? *(const float2*)(p00 + SZ * NC) : make_float2(0.f, 0.f);
    float2 v11 = (yv && zv) ? *(const float2*)(p00 + (SZ + 1) * NC)
                            : make_float2(0.f, 0.f);

    uint4 o;
    o.x = pack_h2(v00.x, v00.y);
    o.y = pack_h2(v01.x, v01.y);
    o.z = pack_h2(v10.x, v10.y);
    o.w = pack_h2(v11.x, v11.y);
    st_evict_last(&g_exp[idx], o, evict_last_policy());
}

struct VoxSetup {
    unsigned off0, off1;   // table element offsets for x0/x1 rows
    float tx, ty, tz;
    float wA, wB;          // x-slot weights (validity folded in)
};

static __device__ __forceinline__ VoxSetup setup_one(
    float cx, float cy, float cz)
{
    VoxSetup s;
    float fx = floorf(cx), fy = floorf(cy), fz = floorf(cz);
    int ix0 = (int)fx, iy0 = (int)fy, iz0 = (int)fz;
    s.tx = cx - fx; s.ty = cy - fy; s.tz = cz - fz;

    bool vyz = (iy0 >= 0) & (iy0 < SY) & (iz0 >= 0) & (iz0 < SZ);
    unsigned cyp = (unsigned)min(max(iy0, 0), SY - 1);
    unsigned czp = (unsigned)min(max(iz0, 0), SZ - 1);

    bool vx0 = (ix0 >= 0) & (ix0 < SX);
    bool vx1 = (ix0 + 1 >= 0) & (ix0 + 1 < SX);
    unsigned cx0 = (unsigned)min(max(ix0, 0), SX - 1);
    unsigned cx1 = (unsigned)min(max(ix0 + 1, 0), SX - 1);

    unsigned base = cyp * SZ + czp;
    s.off0 = base + cx0 * (unsigned)(SY * SZ);
    s.off1 = base + cx1 * (unsigned)(SY * SZ);
    s.wA = (vx0 & vyz) ? (1.0f - s.tx) : 0.0f;
    s.wB = (vx1 & vyz) ? s.tx : 0.0f;
    return s;
}

static __device__ __forceinline__ float2 combine_one(
    const VoxSetup& s, uint4 oA, uint4 oB)
{
    float wy0 = 1.0f - s.ty, wy1 = s.ty;
    float wz0 = 1.0f - s.tz, wz1 = s.tz;
    float w00 = wy0 * wz0, w01 = wy0 * wz1;
    float w10 = wy1 * wz0, w11 = wy1 * wz1;

    float2 a00 = unpack_h2(oA.x), a01 = unpack_h2(oA.y);
    float2 a10 = unpack_h2(oA.z), a11 = unpack_h2(oA.w);
    float2 b00 = unpack_h2(oB.x), b01 = unpack_h2(oB.y);
    float2 b10 = unpack_h2(oB.z), b11 = unpack_h2(oB.w);

    float sA0 = w00 * a00.x + w01 * a01.x + w10 * a10.x + w11 * a11.x;
    float sA1 = w00 * a00.y + w01 * a01.y + w10 * a10.y + w11 * a11.y;
    float sB0 = w00 * b00.x + w01 * b01.x + w10 * b10.x + w11 * b11.x;
    float sB1 = w00 * b00.y + w01 * b01.y + w10 * b10.y + w11 * b11.y;

    return make_float2(s.wA * sA0 + s.wB * sB0,
                       s.wA * sA1 + s.wB * sB1);
}

__global__ __launch_bounds__(256) void resample_main2(
    const float* __restrict__ defb,
    float* __restrict__ outb,
    int npairs)  // VOL/2
{
    int t = blockIdx.x * blockDim.x + threadIdx.x;
    if (t >= npairs) return;

    unsigned long long pol = evict_last_policy();

    const float2* dp = (const float2*)(defb + (size_t)(2 * t) * 3);
    float2 d0 = __ldcs(dp + 0);  // cx0, cy0
    float2 d1 = __ldcs(dp + 1);  // cz0, cx1
    float2 d2 = __ldcs(dp + 2);  // cy1, cz1

    // Phase 1: both voxels' addresses.
    VoxSetup s0 = setup_one(d0.x, d0.y, d1.x);
    VoxSetup s1 = setup_one(d1.y, d2.x, d2.y);

    // Phase 2: issue ALL FOUR gathers back-to-back (max MLP).
    uint4 oA0 = ld_evict_last(&g_exp[s0.off0], pol);
    uint4 oB0 = ld_evict_last(&g_exp[s0.off1], pol);
    uint4 oA1 = ld_evict_last(&g_exp[s1.off0], pol);
    uint4 oB1 = ld_evict_last(&g_exp[s1.off1], pol);

    // Phase 3: combine.
    float2 r0 = combine_one(s0, oA0, oB0);
    float2 r1 = combine_one(s1, oA1, oB1);

    __stcs((float4*)outb + t, make_float4(r0.x, r0.y, r1.x, r1.y));
}

// Exact fallback (R2 kernel) in case sizes differ from the expected shape.
__global__ __launch_bounds__(256) void resample_fallback(
    const float* __restrict__ inp,
    const float* __restrict__ def,
    float* __restrict__ out,
    int total)
{
    int idx = blockIdx.x * blockDim.x + threadIdx.x;
    if (idx >= total) return;
    int b = idx / VOL;
    const float* d = def + (size_t)idx * 3;
    float cx = __ldg(d + 0), cy = __ldg(d + 1), cz = __ldg(d + 2);
    float fx = floorf(cx), fy = floorf(cy), fz = floorf(cz);
    int ix0 = (int)fx, iy0 = (int)fy, iz0 = (int)fz;
    float tx = cx - fx, ty = cy - fy, tz = cz - fz;
    float wxw[2] = {1.0f - tx, tx};
    float wyw[2] = {1.0f - ty, ty};
    float wzw[2] = {1.0f - tz, tz};
    const float* base = inp + (size_t)b * VOL * NC;
    float acc0 = 0.f, acc1 = 0.f;
#pragma unroll
    for (int dx = 0; dx < 2; dx++) {
        int ix = ix0 + dx;
        bool vx = (ix >= 0) & (ix < SX);
        int cxp = min(max(ix, 0), SX - 1);
#pragma unroll
        for (int dy = 0; dy < 2; dy++) {
            int iy = iy0 + dy;
            bool vxy = vx & (iy >= 0) & (iy < SY);
            int cyp = min(max(iy, 0), SY - 1);
            float wxy = wxw[dx] * wyw[dy];
            const float* row = base + ((size_t)cxp * SY + cyp) * SZ * NC;
#pragma unroll
            for (int dz = 0; dz < 2; dz++) {
                int iz = iz0 + dz;
                bool v = vxy & (iz >= 0) & (iz < SZ);
                int czp = min(max(iz, 0), SZ - 1);
                float2 val = __ldg((const float2*)(row + (size_t)czp * NC));
                float w = v ? (wxy * wzw[dz]) : 0.0f;
                acc0 = fmaf(w, val.x, acc0);
                acc1 = fmaf(w, val.y, acc1);
            }
        }
    }
    ((float2*)out)[idx] = make_float2(acc0, acc1);
}

extern "C" void kernel_launch(void* const* d_in, const int* in_sizes, int n_in,
                              void* d_out, int out_size)
{
    int total = out_size / NC;

    const float* inp = (const float*)d_in[0];
    const float* def = (const float*)d_in[1];
    if (n_in >= 2) {
        long long t = (long long)total;
        if ((long long)in_sizes[0] == 3LL * t && (long long)in_sizes[1] == 2LL * t) {
            def = (const float*)d_in[0];
            inp = (const float*)d_in[1];
        }
    }

    const int threads = 256;

    if (total == NB * VOL) {
        int blocksE = (VOL + threads - 1) / threads;
        int npairs = VOL / 2;
        int blocksM = (npairs + threads - 1) / threads;
        for (int b = 0; b < NB; b++) {
            expand_kernel<<<blocksE, threads>>>(
                inp + (size_t)b * VOL * NC, VOL);
            resample_main2<<<blocksM, threads>>>(
                def + (size_t)b * VOL * 3,
                (float*)d_out + (size_t)b * VOL * NC,
                npairs);
        }
    } else {
        int blocks = (total + threads - 1) / threads;
        resample_fallback<<<blocks, threads>>>(inp, def, (float*)d_out, total);
    }
}